// round 12
// baseline (speedup 1.0000x reference)
#include <cuda_runtime.h>
#include <cuda_bf16.h>
#include <math.h>
#include <stdint.h>

#define HID 128
#define TILE 64            // edges per CTA: ONE group of 64, 4-warp cooperative
#define NTHREADS 128       // warp w owns n-quarter w
#define IN_SZ 9
#define FST 12
#define NFRAG (3 * 8 * 16 * 32)

// Pre-packed weight fragments for w1..w3 (m16n8k16 B-frag):
// g_wb[L][q][nt][lane] = uint4 {bhi_r0, bhi_r1, blo_r0, blo_r1}
__device__ uint4 g_wb[NFRAG];
// Layer-0 fragments: K=16 (rows 9..15 zero), 16 n-tiles
__device__ uint4 g_w0[16 * 32];

// v0 -> low half, v1 -> high half (rn rounding per half)
__device__ __forceinline__ uint32_t packbf(float v0, float v1) {
    uint32_t r;
    asm("cvt.rn.bf16x2.f32 %0, %1, %2;" : "=r"(r) : "f"(v1), "f"(v0));
    return r;
}

// Slim hi/lo split: 2 cvt-pack + 2 alu + 2 fadd (bit-identical to per-value rn split).
__device__ __forceinline__ void split2(float v0, float v1, uint32_t& hi, uint32_t& lo) {
    hi = packbf(v0, v1);
    float h0 = __uint_as_float(hi << 16);
    float h1 = __uint_as_float(hi & 0xFFFF0000u);
    lo = packbf(v0 - h0, v1 - h1);
}

__device__ __forceinline__ void mma16816(float* d,
                                         uint32_t a0, uint32_t a1, uint32_t a2, uint32_t a3,
                                         uint32_t b0, uint32_t b1) {
    asm volatile(
        "mma.sync.aligned.m16n8k16.row.col.f32.bf16.bf16.f32 "
        "{%0,%1,%2,%3}, {%4,%5,%6,%7}, {%8,%9}, {%0,%1,%2,%3};"
        : "+f"(d[0]), "+f"(d[1]), "+f"(d[2]), "+f"(d[3])
        : "r"(a0), "r"(a1), "r"(a2), "r"(a3), "r"(b0), "r"(b1));
}

// 3-pass split MMA for one m-tile against 4 B fragments (this warp's n-quarter).
__device__ __forceinline__ void mma_m(
    float (&Dm)[4][4], const uint4& h, const uint4& l, const uint4 (&B)[4])
{
    #pragma unroll
    for (int j = 0; j < 4; j++)
        mma16816(Dm[j], h.x, h.y, h.z, h.w, B[j].x, B[j].y);
    #pragma unroll
    for (int j = 0; j < 4; j++)
        mma16816(Dm[j], h.x, h.y, h.z, h.w, B[j].z, B[j].w);
    #pragma unroll
    for (int j = 0; j < 4; j++)
        mma16816(Dm[j], l.x, l.y, l.z, l.w, B[j].x, B[j].y);
}

// Epilogue: bias+ReLU+split; this warp's 4 nt cover chunks q' = 2nh+{0,1} for all 4 m.
__device__ __forceinline__ void epilogue_sts(
    float (&D)[4][4][4], uint4* __restrict__ Asm, const float* __restrict__ bL,
    int nh, int t, int lane)
{
    #pragma unroll
    for (int p = 0; p < 2; p++) {
        int qp = 2 * nh + p;
        int j0 = 2 * p, j1 = 2 * p + 1;
        float2 bj0 = *(const float2*)(bL + (nh * 4 + j0) * 8 + t * 2);
        float2 bj1 = *(const float2*)(bL + (nh * 4 + j1) * 8 + t * 2);
        #pragma unroll
        for (int m = 0; m < 4; m++) {
            float v0 = fmaxf(D[m][j0][0] + bj0.x, 0.f);
            float v1 = fmaxf(D[m][j0][1] + bj0.y, 0.f);
            float v2 = fmaxf(D[m][j0][2] + bj0.x, 0.f);
            float v3 = fmaxf(D[m][j0][3] + bj0.y, 0.f);
            float u0 = fmaxf(D[m][j1][0] + bj1.x, 0.f);
            float u1 = fmaxf(D[m][j1][1] + bj1.y, 0.f);
            float u2 = fmaxf(D[m][j1][2] + bj1.x, 0.f);
            float u3 = fmaxf(D[m][j1][3] + bj1.y, 0.f);
            uint4 hi, lo;
            split2(v0, v1, hi.x, lo.x);
            split2(v2, v3, hi.y, lo.y);
            split2(u0, u1, hi.z, lo.z);
            split2(u2, u3, hi.w, lo.w);
            uint4* pp = Asm + ((qp * 4 + m) * 2) * 32;
            pp[lane]      = hi;
            pp[32 + lane] = lo;
        }
    }
}

// ---------------- prep (+ output zeroing; keeps launch count at 2) ----------------
__global__ void prep_kernel(const float* __restrict__ w0,
                            const float* __restrict__ w1,
                            const float* __restrict__ w2,
                            const float* __restrict__ w3,
                            float* __restrict__ out, int out_n) {
    int s = blockIdx.x * blockDim.x + threadIdx.x;
    if (s < out_n) out[s] = 0.0f;
    if (s < 16 * 32) {
        int lane = s & 31;
        int nt   = s >> 5;
        int g = lane >> 2, t = lane & 3;
        int n  = nt * 8 + g;
        int k0 = t * 2;
        float v00 = w0[k0 * HID + n];
        float v01 = w0[(k0 + 1) * HID + n];
        float v10 = (t == 0) ? w0[8 * HID + n] : 0.0f;
        float v11 = 0.0f;
        uint4 o;
        split2(v00, v01, o.x, o.z);
        split2(v10, v11, o.y, o.w);
        g_w0[s] = o;
    }
    if (s < NFRAG) {
        int lane = s & 31;
        int nt   = (s >> 5) & 15;
        int q    = (s >> 9) & 7;
        int L    = s >> 12;
        int g = lane >> 2, t = lane & 3;
        int n  = nt * 8 + g;
        int k0 = q * 16 + t * 2;
        const float* W = (L == 0) ? w1 : (L == 1) ? w2 : w3;
        float v00 = W[k0 * HID + n];
        float v01 = W[(k0 + 1) * HID + n];
        float v10 = W[(k0 + 8) * HID + n];
        float v11 = W[(k0 + 9) * HID + n];
        uint4 o;
        split2(v00, v01, o.x, o.z);
        split2(v10, v11, o.y, o.w);
        g_wb[s] = o;
    }
}

// ---------------- main kernel ----------------
__global__ __launch_bounds__(NTHREADS, 5)
void gnn_mma_kernel(
    const float* __restrict__ pos,
    const float* __restrict__ vel,
    const float* __restrict__ a,
    const float* __restrict__ vnorm,
    const float* __restrict__ b0,
    const float* __restrict__ b1, const float* __restrict__ b2, const float* __restrict__ b3,
    const float* __restrict__ w4, const float* __restrict__ b4,
    const int* __restrict__ ei,
    const int* __restrict__ data_id_p,
    float* __restrict__ out,
    int E, int N)
{
    __shared__ float feats[TILE * FST];
    __shared__ int   sdst[TILE];
    // A fragments: [q(8)][m(4)][hi/lo(2)][lane(32)] uint4 = 32 KB
    __shared__ uint4 Asm[8 * 4 * 2 * 32];

    const int tid  = threadIdx.x;
    const int nh   = tid >> 5;        // warp = n-quarter
    const int lane = tid & 31;
    const int g = lane >> 2, t = lane & 3;

    // ---- feature build: 1 thread per edge (tid < 64) ----
    if (tid < TILE) {
        int e = blockIdx.x * TILE + tid;
        float* f = feats + tid * FST;
        int dstv = -1;
        if (e < E) {
            dstv    = ei[e];
            int src = ei[E + e];
            float inv_vn = 1.0f / vnorm[0];
            float dpx = (pos[2 * src]     - pos[2 * dstv])     * 10.0f;  // / MAX_RADIUS
            float dpy = (pos[2 * src + 1] - pos[2 * dstv + 1]) * 10.0f;
            f[0] = dpx; f[1] = dpy;
            f[2] = sqrtf(dpx * dpx + dpy * dpy);
            f[3] = vel[2 * dstv]     * inv_vn;
            f[4] = vel[2 * dstv + 1] * inv_vn;
            f[5] = vel[2 * src]      * inv_vn;
            f[6] = vel[2 * src + 1]  * inv_vn;
            int did = *data_id_p;
            const float* emb = a + ((size_t)did * N + dstv) * 2;
            f[7] = emb[0]; f[8] = emb[1];
        } else {
            #pragma unroll
            for (int k = 0; k < IN_SZ; k++) f[k] = 0.0f;
        }
        f[9] = 0.0f;
        sdst[tid] = dstv;
    }
    __syncthreads();

    float D[4][4][4];

    // ---- layer 0 via MMA (K=16, zero-padded), n-quarter per warp ----
    {
        #pragma unroll
        for (int m = 0; m < 4; m++)
            #pragma unroll
            for (int j = 0; j < 4; j++) {
                D[m][j][0] = 0.f; D[m][j][1] = 0.f; D[m][j][2] = 0.f; D[m][j][3] = 0.f;
            }
        uint4 B[4];
        #pragma unroll
        for (int j = 0; j < 4; j++) B[j] = g_w0[(nh * 4 + j) * 32 + lane];
        #pragma unroll
        for (int m = 0; m < 4; m++) {
            const float* r0p = feats + (m * 16 + g)     * FST;
            const float* r1p = feats + (m * 16 + g + 8) * FST;
            float2 p0 = *(const float2*)(r0p + 2 * t);
            float2 p1 = *(const float2*)(r1p + 2 * t);
            float2 p2 = make_float2(0.f, 0.f), p3 = make_float2(0.f, 0.f);
            if (t == 0) {
                p2 = *(const float2*)(r0p + 8);
                p3 = *(const float2*)(r1p + 8);
            }
            uint4 h, l;
            split2(p0.x, p0.y, h.x, l.x);
            split2(p1.x, p1.y, h.y, l.y);
            split2(p2.x, p2.y, h.z, l.z);
            split2(p3.x, p3.y, h.w, l.w);
            mma_m(D[m], h, l, B);
        }
        epilogue_sts(D, Asm, b0, nh, t, lane);
    }
    __syncthreads();

    // ---- hidden layers 1 and 2 ----
    #pragma unroll 1
    for (int L = 0; L < 2; L++) {
        #pragma unroll
        for (int m = 0; m < 4; m++)
            #pragma unroll
            for (int j = 0; j < 4; j++) {
                D[m][j][0] = 0.f; D[m][j][1] = 0.f; D[m][j][2] = 0.f; D[m][j][3] = 0.f;
            }
        const uint4* wbL = g_wb + (size_t)L * (8 * 16 * 32);
        #pragma unroll
        for (int q = 0; q < 8; q++) {
            uint4 B[4];
            #pragma unroll
            for (int j = 0; j < 4; j++) B[j] = wbL[(q * 16 + nh * 4 + j) * 32 + lane];
            #pragma unroll
            for (int m = 0; m < 4; m++) {
                const uint4* ap = Asm + ((q * 4 + m) * 2) * 32;
                uint4 h = ap[lane];
                uint4 l = ap[32 + lane];
                mma_m(D[m], h, l, B);
            }
        }
        __syncthreads();   // all A reads done before overwrite
        epilogue_sts(D, Asm, (L == 0) ? b1 : b2, nh, t, lane);
        __syncthreads();   // writes visible to all warps
    }

    // ---- layer 3 (w3) + fused layer 4 (w4, partial over this warp's n-quarter) ----
    {
        #pragma unroll
        for (int m = 0; m < 4; m++)
            #pragma unroll
            for (int j = 0; j < 4; j++) {
                D[m][j][0] = 0.f; D[m][j][1] = 0.f; D[m][j][2] = 0.f; D[m][j][3] = 0.f;
            }
        const uint4* wbL = g_wb + (size_t)2 * (8 * 16 * 32);
        #pragma unroll
        for (int q = 0; q < 8; q++) {
            uint4 B[4];
            #pragma unroll
            for (int j = 0; j < 4; j++) B[j] = wbL[(q * 16 + nh * 4 + j) * 32 + lane];
            #pragma unroll
            for (int m = 0; m < 4; m++) {
                const uint4* ap = Asm + ((q * 4 + m) * 2) * 32;
                uint4 h = ap[lane];
                uint4 l = ap[32 + lane];
                mma_m(D[m], h, l, B);
            }
        }

        float m0g[4], m1g[4], m0h[4], m1h[4];
        #pragma unroll
        for (int m = 0; m < 4; m++) { m0g[m] = 0.f; m1g[m] = 0.f; m0h[m] = 0.f; m1h[m] = 0.f; }
        #pragma unroll
        for (int j = 0; j < 4; j++) {
            int n0 = (nh * 4 + j) * 8 + t * 2;
            float2 bj = *(const float2*)(b3 + n0);
            float4 w4v = *(const float4*)(w4 + 2 * n0);
            #pragma unroll
            for (int m = 0; m < 4; m++) {
                float v0 = fmaxf(D[m][j][0] + bj.x, 0.f);
                float v1 = fmaxf(D[m][j][1] + bj.y, 0.f);
                float v2 = fmaxf(D[m][j][2] + bj.x, 0.f);
                float v3 = fmaxf(D[m][j][3] + bj.y, 0.f);
                m0g[m] = fmaf(v0, w4v.x, fmaf(v1, w4v.z, m0g[m]));
                m1g[m] = fmaf(v0, w4v.y, fmaf(v1, w4v.w, m1g[m]));
                m0h[m] = fmaf(v2, w4v.x, fmaf(v3, w4v.z, m0h[m]));
                m1h[m] = fmaf(v2, w4v.y, fmaf(v3, w4v.w, m1h[m]));
            }
        }
        #pragma unroll
        for (int d = 1; d <= 2; d <<= 1) {
            #pragma unroll
            for (int m = 0; m < 4; m++) {
                m0g[m] += __shfl_xor_sync(0xFFFFFFFFu, m0g[m], d);
                m1g[m] += __shfl_xor_sync(0xFFFFFFFFu, m1g[m], d);
                m0h[m] += __shfl_xor_sync(0xFFFFFFFFu, m0h[m], d);
                m1h[m] += __shfl_xor_sync(0xFFFFFFFFu, m1h[m], d);
            }
        }
        if (t == 0) {
            // bias added once per edge (by warp nh == 0)
            float bb0 = (nh == 0) ? b4[0] : 0.f;
            float bb1 = (nh == 0) ? b4[1] : 0.f;
            #pragma unroll
            for (int m = 0; m < 4; m++) {
                int d0 = sdst[m * 16 + g];
                if (d0 >= 0) {
                    atomicAdd(&out[2 * d0],     m0g[m] + bb0);
                    atomicAdd(&out[2 * d0 + 1], m1g[m] + bb1);
                }
                int d1 = sdst[m * 16 + g + 8];
                if (d1 >= 0) {
                    atomicAdd(&out[2 * d1],     m0h[m] + bb0);
                    atomicAdd(&out[2 * d1 + 1], m1h[m] + bb1);
                }
            }
        }
    }
}

extern "C" void kernel_launch(void* const* d_in, const int* in_sizes, int n_in,
                              void* d_out, int out_size) {
    const float* pos   = (const float*)d_in[0];
    const float* vel   = (const float*)d_in[1];
    const float* a     = (const float*)d_in[2];
    const float* vnorm = (const float*)d_in[3];
    const float* w0    = (const float*)d_in[4];
    const float* b0    = (const float*)d_in[5];
    const float* w1    = (const float*)d_in[6];
    const float* b1    = (const float*)d_in[7];
    const float* w2    = (const float*)d_in[8];
    const float* b2    = (const float*)d_in[9];
    const float* w3    = (const float*)d_in[10];
    const float* b3    = (const float*)d_in[11];
    const float* w4    = (const float*)d_in[12];
    const float* b4    = (const float*)d_in[13];
    const int*   ei    = (const int*)d_in[14];    // int32 [2, E]
    const int*   did   = (const int*)d_in[15];
    float*       out   = (float*)d_out;

    int E = in_sizes[14] / 2;
    int N = in_sizes[0] / 2;

    int prep_n = (out_size > NFRAG) ? out_size : NFRAG;
    prep_kernel<<<(prep_n + 255) / 256, 256>>>(w0, w1, w2, w3, out, out_size);

    int tiles = (E + TILE - 1) / TILE;
    gnn_mma_kernel<<<tiles, NTHREADS>>>(
        pos, vel, a, vnorm, b0, b1, b2, b3, w4, b4,
        ei, did, out, E, N);
}

// round 13
// speedup vs baseline: 1.1918x; 1.1918x over previous
#include <cuda_runtime.h>
#include <cuda_bf16.h>
#include <math.h>
#include <stdint.h>

#define HID 128
#define TILE 64            // edges per CTA: ONE group of 64, 4-warp cooperative
#define NTHREADS 128       // warp w owns n-quarter w
#define IN_SZ 9
#define FST 12
#define NFRAG (3 * 8 * 16 * 32)

// Pre-packed weight fragments for w1..w3 (m16n8k16 B-frag):
// g_wb[L][q][nt][lane] = uint4 {bhi_r0, bhi_r1, blo_r0, blo_r1}
__device__ uint4 g_wb[NFRAG];
// Layer-0 fragments: K=16 (rows 9..15 zero), 16 n-tiles
__device__ uint4 g_w0[16 * 32];

// v0 -> low half, v1 -> high half (rn rounding per half)
__device__ __forceinline__ uint32_t packbf(float v0, float v1) {
    uint32_t r;
    asm("cvt.rn.bf16x2.f32 %0, %1, %2;" : "=r"(r) : "f"(v1), "f"(v0));
    return r;
}

// Slim hi/lo split: 2 cvt-pack + 2 alu + 2 fadd (bit-identical to per-value rn split).
__device__ __forceinline__ void split2(float v0, float v1, uint32_t& hi, uint32_t& lo) {
    hi = packbf(v0, v1);
    float h0 = __uint_as_float(hi << 16);
    float h1 = __uint_as_float(hi & 0xFFFF0000u);
    lo = packbf(v0 - h0, v1 - h1);
}

__device__ __forceinline__ void mma16816(float* d,
                                         uint32_t a0, uint32_t a1, uint32_t a2, uint32_t a3,
                                         uint32_t b0, uint32_t b1) {
    asm volatile(
        "mma.sync.aligned.m16n8k16.row.col.f32.bf16.bf16.f32 "
        "{%0,%1,%2,%3}, {%4,%5,%6,%7}, {%8,%9}, {%0,%1,%2,%3};"
        : "+f"(d[0]), "+f"(d[1]), "+f"(d[2]), "+f"(d[3])
        : "r"(a0), "r"(a1), "r"(a2), "r"(a3), "r"(b0), "r"(b1));
}

// 3-pass split MMA for one m-tile against 4 B fragments (this warp's n-quarter).
__device__ __forceinline__ void mma_m(
    float (&Dm)[4][4], const uint4& h, const uint4& l, const uint4 (&B)[4])
{
    #pragma unroll
    for (int j = 0; j < 4; j++)
        mma16816(Dm[j], h.x, h.y, h.z, h.w, B[j].x, B[j].y);
    #pragma unroll
    for (int j = 0; j < 4; j++)
        mma16816(Dm[j], h.x, h.y, h.z, h.w, B[j].z, B[j].w);
    #pragma unroll
    for (int j = 0; j < 4; j++)
        mma16816(Dm[j], l.x, l.y, l.z, l.w, B[j].x, B[j].y);
}

// Epilogue: bias+ReLU+split; this warp's 4 nt cover chunks q' = 2nh+{0,1} for all 4 m.
__device__ __forceinline__ void epilogue_sts(
    float (&D)[4][4][4], uint4* __restrict__ Asm, const float* __restrict__ bL,
    int nh, int t, int lane)
{
    #pragma unroll
    for (int p = 0; p < 2; p++) {
        int qp = 2 * nh + p;
        int j0 = 2 * p, j1 = 2 * p + 1;
        float2 bj0 = *(const float2*)(bL + (nh * 4 + j0) * 8 + t * 2);
        float2 bj1 = *(const float2*)(bL + (nh * 4 + j1) * 8 + t * 2);
        #pragma unroll
        for (int m = 0; m < 4; m++) {
            float v0 = fmaxf(D[m][j0][0] + bj0.x, 0.f);
            float v1 = fmaxf(D[m][j0][1] + bj0.y, 0.f);
            float v2 = fmaxf(D[m][j0][2] + bj0.x, 0.f);
            float v3 = fmaxf(D[m][j0][3] + bj0.y, 0.f);
            float u0 = fmaxf(D[m][j1][0] + bj1.x, 0.f);
            float u1 = fmaxf(D[m][j1][1] + bj1.y, 0.f);
            float u2 = fmaxf(D[m][j1][2] + bj1.x, 0.f);
            float u3 = fmaxf(D[m][j1][3] + bj1.y, 0.f);
            uint4 hi, lo;
            split2(v0, v1, hi.x, lo.x);
            split2(v2, v3, hi.y, lo.y);
            split2(u0, u1, hi.z, lo.z);
            split2(u2, u3, hi.w, lo.w);
            uint4* pp = Asm + ((qp * 4 + m) * 2) * 32;
            pp[lane]      = hi;
            pp[32 + lane] = lo;
        }
    }
}

// ---------------- prep (+ output zeroing; keeps launch count at 2) ----------------
__global__ void prep_kernel(const float* __restrict__ w0,
                            const float* __restrict__ w1,
                            const float* __restrict__ w2,
                            const float* __restrict__ w3,
                            float* __restrict__ out, int out_n) {
    int s = blockIdx.x * blockDim.x + threadIdx.x;
    if (s < out_n) out[s] = 0.0f;
    if (s < 16 * 32) {
        int lane = s & 31;
        int nt   = s >> 5;
        int g = lane >> 2, t = lane & 3;
        int n  = nt * 8 + g;
        int k0 = t * 2;
        float v00 = w0[k0 * HID + n];
        float v01 = w0[(k0 + 1) * HID + n];
        float v10 = (t == 0) ? w0[8 * HID + n] : 0.0f;
        float v11 = 0.0f;
        uint4 o;
        split2(v00, v01, o.x, o.z);
        split2(v10, v11, o.y, o.w);
        g_w0[s] = o;
    }
    if (s < NFRAG) {
        int lane = s & 31;
        int nt   = (s >> 5) & 15;
        int q    = (s >> 9) & 7;
        int L    = s >> 12;
        int g = lane >> 2, t = lane & 3;
        int n  = nt * 8 + g;
        int k0 = q * 16 + t * 2;
        const float* W = (L == 0) ? w1 : (L == 1) ? w2 : w3;
        float v00 = W[k0 * HID + n];
        float v01 = W[(k0 + 1) * HID + n];
        float v10 = W[(k0 + 8) * HID + n];
        float v11 = W[(k0 + 9) * HID + n];
        uint4 o;
        split2(v00, v01, o.x, o.z);
        split2(v10, v11, o.y, o.w);
        g_wb[s] = o;
    }
}

// ---------------- main kernel ----------------
__global__ __launch_bounds__(NTHREADS, 4)
void gnn_mma_kernel(
    const float* __restrict__ pos,
    const float* __restrict__ vel,
    const float* __restrict__ a,
    const float* __restrict__ vnorm,
    const float* __restrict__ b0,
    const float* __restrict__ b1, const float* __restrict__ b2, const float* __restrict__ b3,
    const float* __restrict__ w4, const float* __restrict__ b4,
    const int* __restrict__ ei,
    const int* __restrict__ data_id_p,
    float* __restrict__ out,
    int E, int N)
{
    __shared__ float feats[TILE * FST];
    __shared__ int   sdst[TILE];
    // A fragments: [q(8)][m(4)][hi/lo(2)][lane(32)] uint4 = 32 KB
    __shared__ uint4 Asm[8 * 4 * 2 * 32];

    const int tid  = threadIdx.x;
    const int nh   = tid >> 5;        // warp = n-quarter
    const int lane = tid & 31;
    const int g = lane >> 2, t = lane & 3;

    // ---- feature build: 1 thread per edge (tid < 64) ----
    if (tid < TILE) {
        int e = blockIdx.x * TILE + tid;
        float* f = feats + tid * FST;
        int dstv = -1;
        if (e < E) {
            dstv    = ei[e];
            int src = ei[E + e];
            float inv_vn = 1.0f / vnorm[0];
            float dpx = (pos[2 * src]     - pos[2 * dstv])     * 10.0f;  // / MAX_RADIUS
            float dpy = (pos[2 * src + 1] - pos[2 * dstv + 1]) * 10.0f;
            f[0] = dpx; f[1] = dpy;
            f[2] = sqrtf(dpx * dpx + dpy * dpy);
            f[3] = vel[2 * dstv]     * inv_vn;
            f[4] = vel[2 * dstv + 1] * inv_vn;
            f[5] = vel[2 * src]      * inv_vn;
            f[6] = vel[2 * src + 1]  * inv_vn;
            int did = *data_id_p;
            const float* emb = a + ((size_t)did * N + dstv) * 2;
            f[7] = emb[0]; f[8] = emb[1];
        } else {
            #pragma unroll
            for (int k = 0; k < IN_SZ; k++) f[k] = 0.0f;
        }
        f[9] = 0.0f;
        sdst[tid] = dstv;
    }
    __syncthreads();

    float D[4][4][4];

    // ---- layer 0 via MMA (K=16, zero-padded), n-quarter per warp ----
    {
        #pragma unroll
        for (int m = 0; m < 4; m++)
            #pragma unroll
            for (int j = 0; j < 4; j++) {
                D[m][j][0] = 0.f; D[m][j][1] = 0.f; D[m][j][2] = 0.f; D[m][j][3] = 0.f;
            }
        uint4 B[4];
        #pragma unroll
        for (int j = 0; j < 4; j++) B[j] = g_w0[(nh * 4 + j) * 32 + lane];
        #pragma unroll
        for (int m = 0; m < 4; m++) {
            const float* r0p = feats + (m * 16 + g)     * FST;
            const float* r1p = feats + (m * 16 + g + 8) * FST;
            float2 p0 = *(const float2*)(r0p + 2 * t);
            float2 p1 = *(const float2*)(r1p + 2 * t);
            float2 p2 = make_float2(0.f, 0.f), p3 = make_float2(0.f, 0.f);
            if (t == 0) {
                p2 = *(const float2*)(r0p + 8);
                p3 = *(const float2*)(r1p + 8);
            }
            uint4 h, l;
            split2(p0.x, p0.y, h.x, l.x);
            split2(p1.x, p1.y, h.y, l.y);
            split2(p2.x, p2.y, h.z, l.z);
            split2(p3.x, p3.y, h.w, l.w);
            mma_m(D[m], h, l, B);
        }
        epilogue_sts(D, Asm, b0, nh, t, lane);
    }
    __syncthreads();

    // ---- hidden layers 1 and 2 ----
    #pragma unroll 1
    for (int L = 0; L < 2; L++) {
        #pragma unroll
        for (int m = 0; m < 4; m++)
            #pragma unroll
            for (int j = 0; j < 4; j++) {
                D[m][j][0] = 0.f; D[m][j][1] = 0.f; D[m][j][2] = 0.f; D[m][j][3] = 0.f;
            }
        const uint4* wbL = g_wb + (size_t)L * (8 * 16 * 32);
        #pragma unroll
        for (int q = 0; q < 8; q++) {
            uint4 B[4];
            #pragma unroll
            for (int j = 0; j < 4; j++) B[j] = wbL[(q * 16 + nh * 4 + j) * 32 + lane];
            #pragma unroll
            for (int m = 0; m < 4; m++) {
                const uint4* ap = Asm + ((q * 4 + m) * 2) * 32;
                uint4 h = ap[lane];
                uint4 l = ap[32 + lane];
                mma_m(D[m], h, l, B);
            }
        }
        __syncthreads();   // all A reads done before overwrite
        epilogue_sts(D, Asm, (L == 0) ? b1 : b2, nh, t, lane);
        __syncthreads();   // writes visible to all warps
    }

    // ---- layer 3 (w3) + fused layer 4 (w4, partial over this warp's n-quarter) ----
    {
        #pragma unroll
        for (int m = 0; m < 4; m++)
            #pragma unroll
            for (int j = 0; j < 4; j++) {
                D[m][j][0] = 0.f; D[m][j][1] = 0.f; D[m][j][2] = 0.f; D[m][j][3] = 0.f;
            }
        const uint4* wbL = g_wb + (size_t)2 * (8 * 16 * 32);
        #pragma unroll
        for (int q = 0; q < 8; q++) {
            uint4 B[4];
            #pragma unroll
            for (int j = 0; j < 4; j++) B[j] = wbL[(q * 16 + nh * 4 + j) * 32 + lane];
            #pragma unroll
            for (int m = 0; m < 4; m++) {
                const uint4* ap = Asm + ((q * 4 + m) * 2) * 32;
                uint4 h = ap[lane];
                uint4 l = ap[32 + lane];
                mma_m(D[m], h, l, B);
            }
        }

        float m0g[4], m1g[4], m0h[4], m1h[4];
        #pragma unroll
        for (int m = 0; m < 4; m++) { m0g[m] = 0.f; m1g[m] = 0.f; m0h[m] = 0.f; m1h[m] = 0.f; }
        #pragma unroll
        for (int j = 0; j < 4; j++) {
            int n0 = (nh * 4 + j) * 8 + t * 2;
            float2 bj = *(const float2*)(b3 + n0);
            float4 w4v = *(const float4*)(w4 + 2 * n0);
            #pragma unroll
            for (int m = 0; m < 4; m++) {
                float v0 = fmaxf(D[m][j][0] + bj.x, 0.f);
                float v1 = fmaxf(D[m][j][1] + bj.y, 0.f);
                float v2 = fmaxf(D[m][j][2] + bj.x, 0.f);
                float v3 = fmaxf(D[m][j][3] + bj.y, 0.f);
                m0g[m] = fmaf(v0, w4v.x, fmaf(v1, w4v.z, m0g[m]));
                m1g[m] = fmaf(v0, w4v.y, fmaf(v1, w4v.w, m1g[m]));
                m0h[m] = fmaf(v2, w4v.x, fmaf(v3, w4v.z, m0h[m]));
                m1h[m] = fmaf(v2, w4v.y, fmaf(v3, w4v.w, m1h[m]));
            }
        }
        #pragma unroll
        for (int d = 1; d <= 2; d <<= 1) {
            #pragma unroll
            for (int m = 0; m < 4; m++) {
                m0g[m] += __shfl_xor_sync(0xFFFFFFFFu, m0g[m], d);
                m1g[m] += __shfl_xor_sync(0xFFFFFFFFu, m1g[m], d);
                m0h[m] += __shfl_xor_sync(0xFFFFFFFFu, m0h[m], d);
                m1h[m] += __shfl_xor_sync(0xFFFFFFFFu, m1h[m], d);
            }
        }
        if (t == 0) {
            // bias added once per edge (by warp nh == 0)
            float bb0 = (nh == 0) ? b4[0] : 0.f;
            float bb1 = (nh == 0) ? b4[1] : 0.f;
            #pragma unroll
            for (int m = 0; m < 4; m++) {
                int d0 = sdst[m * 16 + g];
                if (d0 >= 0) {
                    atomicAdd(&out[2 * d0],     m0g[m] + bb0);
                    atomicAdd(&out[2 * d0 + 1], m1g[m] + bb1);
                }
                int d1 = sdst[m * 16 + g + 8];
                if (d1 >= 0) {
                    atomicAdd(&out[2 * d1],     m0h[m] + bb0);
                    atomicAdd(&out[2 * d1 + 1], m1h[m] + bb1);
                }
            }
        }
    }
}

extern "C" void kernel_launch(void* const* d_in, const int* in_sizes, int n_in,
                              void* d_out, int out_size) {
    const float* pos   = (const float*)d_in[0];
    const float* vel   = (const float*)d_in[1];
    const float* a     = (const float*)d_in[2];
    const float* vnorm = (const float*)d_in[3];
    const float* w0    = (const float*)d_in[4];
    const float* b0    = (const float*)d_in[5];
    const float* w1    = (const float*)d_in[6];
    const float* b1    = (const float*)d_in[7];
    const float* w2    = (const float*)d_in[8];
    const float* b2    = (const float*)d_in[9];
    const float* w3    = (const float*)d_in[10];
    const float* b3    = (const float*)d_in[11];
    const float* w4    = (const float*)d_in[12];
    const float* b4    = (const float*)d_in[13];
    const int*   ei    = (const int*)d_in[14];    // int32 [2, E]
    const int*   did   = (const int*)d_in[15];
    float*       out   = (float*)d_out;

    int E = in_sizes[14] / 2;
    int N = in_sizes[0] / 2;

    int prep_n = (out_size > NFRAG) ? out_size : NFRAG;
    prep_kernel<<<(prep_n + 255) / 256, 256>>>(w0, w1, w2, w3, out, out_size);

    int tiles = (E + TILE - 1) / TILE;
    gnn_mma_kernel<<<tiles, NTHREADS>>>(
        pos, vel, a, vnorm, b0, b1, b2, b3, w4, b4,
        ei, did, out, E, N);
}